// round 14
// baseline (speedup 1.0000x reference)
#include <cuda_runtime.h>
#include <math.h>

#define N_NODES 50000
#define N_EDGES 1250000
#define D_SIMD  256
#define F_ATTN  64
#define SLOPE   0.2f
#define CAP     128      // max in-degree capacity (Poisson(25): max ~55 for this fixed input)

// single-wave grid at 3 blocks/SM on 148 SMs = 444 resident CTAs
#define PROJ_BLOCKS 296
#define SCAT_BLOCKS 148

// ---------------- scratch (device globals; no allocations allowed) ----------
__device__ float g_z[N_NODES * F_ATTN];              // projected features [N,64]
__device__ int   g_counts[N_NODES];                  // in-degree / slot cursor
__device__ int   g_slots[(size_t)N_NODES * CAP];     // src node per dst slot
__device__ int   g_list[2][N_NODES];                 // nodes partitioned by type
__device__ int   g_cnt2[2];                          // list sizes

// ---------------- packed f32x2 helpers ---------------------------------------
__device__ __forceinline__ unsigned long long pack2_dup(float x) {
    unsigned long long r;
    asm("mov.b64 %0, {%1, %1};" : "=l"(r) : "f"(x));
    return r;
}
__device__ __forceinline__ void ffma2(unsigned long long &c,
                                      unsigned long long a,
                                      unsigned long long b) {
    asm("fma.rn.f32x2 %0, %1, %2, %0;" : "+l"(c) : "l"(a), "l"(b));
}
// reload that the compiler cannot CSE with the earlier C++ load
__device__ __forceinline__ float4 ld_nc_v4(const float4* p) {
    float4 v;
    asm("ld.global.nc.v4.f32 {%0,%1,%2,%3}, [%4];"
        : "=f"(v.x), "=f"(v.y), "=f"(v.z), "=f"(v.w) : "l"(p));
    return v;
}

// ---------------- KA: zero counters (counts + type counters) -----------------
__global__ void prep_kernel() {
    int n = blockIdx.x * blockDim.x + threadIdx.x;
    if (n < N_NODES) g_counts[n] = 0;
    if (n < 2) g_cnt2[n] = 0;
}

// ---------------- KA2: partition nodes by type -------------------------------
__global__ void build_kernel(const int* __restrict__ node_type) {
    int n = blockIdx.x * blockDim.x + threadIdx.x;
    if (n >= N_NODES) return;
    int t = node_type[n];                  // 1 -> d_sim@W_d ; 0 -> m_sim@W_m
    int w = (t == 1) ? 1 : 0;
    int p = atomicAdd(&g_cnt2[w], 1);
    g_list[w][p] = n;
}

// ---------------- KB: single-wave fused projection + scatter -----------------
// Blocks [0, PROJ_BLOCKS): projection z = sim @ W, TILE=128 nodes,
//   4 nodes/thread, 8 f-cols/thread, FFMA2 accumulators, W staged via smem.
// Blocks [PROJ_BLOCKS, PROJ+SCAT): grid-stride edge scatter.
// All 444 blocks resident in one wave -> true overlap.
__global__ void __launch_bounds__(256, 3) work_kernel(
    const float* __restrict__ d_sim,
    const float* __restrict__ m_sim,
    const float* __restrict__ W_d,
    const float* __restrict__ W_m,
    const int*   __restrict__ src,
    const int*   __restrict__ dst)
{
    __shared__ float sW[128 * F_ATTN];          // 32 KB k-chunk of W

    if (blockIdx.x >= PROJ_BLOCKS) {
        const int sbid = blockIdx.x - PROJ_BLOCKS;
        const int stride = SCAT_BLOCKS * 256;
        for (int j = sbid * 256 + threadIdx.x; j < N_EDGES; j += stride) {
            int d = dst[j];
            int pos = atomicAdd(&g_counts[d], 1);
            if (pos < CAP) g_slots[(size_t)d * CAP + pos] = src[j];
        }
        return;
    }

    // ---------------- projection part ----------------
    const int cnt1 = g_cnt2[1];
    const int cnt0 = g_cnt2[0];
    const int tiles1 = (cnt1 + 127) >> 7;
    const int tiles0 = (cnt0 + 127) >> 7;
    const int total = tiles1 + tiles0;

    const int fgrp = threadIdx.x & 7;
    const int ngrp = threadIdx.x >> 3;          // 0..31
    const int fb = fgrp * 8;

    for (int t = blockIdx.x; t < total; t += PROJ_BLOCKS) {
        const int w   = (t < tiles1) ? 1 : 0;
        const int lt  = (w == 1) ? t : (t - tiles1);
        const float* __restrict__ sim = (w == 1) ? d_sim : m_sim;
        const float* __restrict__ W   = (w == 1) ? W_d  : W_m;
        const int*   __restrict__ list = g_list[w];
        const int count = (w == 1) ? cnt1 : cnt0;

        const int base = lt * 128;
        int n[4]; bool valid[4];
        const float4* sv[4];
        unsigned long long acc2[4][4];          // 4 packed pairs per node = 8 cols
        #pragma unroll
        for (int i = 0; i < 4; i++) {
            int li = base + ngrp + 32 * i;
            valid[i] = (li < count);
            n[i] = valid[i] ? list[li] : 0;
            sv[i] = (const float4*)(sim + (size_t)n[i] * D_SIMD);
            #pragma unroll
            for (int j = 0; j < 4; j++) acc2[i][j] = 0ull;
        }

        for (int kt = 0; kt < 2; kt++) {
            __syncthreads();
            {
                const float4* w4 = (const float4*)(W + kt * 128 * F_ATTN);
                float4* s4 = (float4*)sW;
                for (int idx = threadIdx.x; idx < 128 * F_ATTN / 4; idx += 256)
                    s4[idx] = w4[idx];
            }
            __syncthreads();

            #pragma unroll 4
            for (int k4 = 0; k4 < 32; k4++) {
                float4 s4v[4];
                #pragma unroll
                for (int i = 0; i < 4; i++) s4v[i] = sv[i][kt * 32 + k4];
                #pragma unroll
                for (int c = 0; c < 4; c++) {
                    int kl = k4 * 4 + c;
                    const ulonglong2* wp =
                        (const ulonglong2*)&sW[kl * F_ATTN + fb];
                    ulonglong2 wA = wp[0];
                    ulonglong2 wB = wp[1];
                    #pragma unroll
                    for (int i = 0; i < 4; i++) {
                        float sk = (c == 0) ? s4v[i].x :
                                   (c == 1) ? s4v[i].y :
                                   (c == 2) ? s4v[i].z : s4v[i].w;
                        unsigned long long sk2 = pack2_dup(sk);
                        ffma2(acc2[i][0], wA.x, sk2);
                        ffma2(acc2[i][1], wA.y, sk2);
                        ffma2(acc2[i][2], wB.x, sk2);
                        ffma2(acc2[i][3], wB.y, sk2);
                    }
                }
            }
        }

        #pragma unroll
        for (int i = 0; i < 4; i++) {
            if (valid[i]) {
                ulonglong2* zp = (ulonglong2*)&g_z[(size_t)n[i] * F_ATTN + fb];
                ulonglong2 v0; v0.x = acc2[i][0]; v0.y = acc2[i][1];
                ulonglong2 v1; v1.x = acc2[i][2]; v1.y = acc2[i][3];
                zp[0] = v0;
                zp[1] = v1;
            }
        }
    }
}

// ---------------- KC: chunked-softmax aggregation + ELU ----------------------
// TWO nodes per warp: lanes 0-15 node A, lanes 16-31 node B; each lane holds
// 4 feature cols (float4). Per 8-edge chunk: dot phase (short-lived zs regs),
// chunk max, independent exps, then L1-hit RELOAD of z rows for accumulation.
__global__ void __launch_bounds__(256) aggregate_kernel(float* __restrict__ out) {
    int wg   = (blockIdx.x * blockDim.x + threadIdx.x) >> 5;
    int lane = threadIdx.x & 31;
    int half = lane >> 4;
    int hl   = lane & 15;
    int node = wg * 2 + half;
    if (node >= N_NODES) return;

    int deg = g_counts[node];
    if (deg > CAP) deg = CAP;
    int degO = __shfl_xor_sync(0xffffffffu, deg, 16);
    int dmax = (deg > degO) ? deg : degO;
    int nch = (dmax + 7) >> 3;

    const float4* zb4 = (const float4*)g_z;
    float4 zd = zb4[(size_t)node * 16 + hl];
    const int* slots = g_slots + (size_t)node * CAP;

    float m = -3.0e38f, d = 0.0f;
    float ax = 0.0f, ay = 0.0f, az = 0.0f, aw = 0.0f;

    for (int c = 0; c < nch; c++) {
        int i0 = c * 8;
        int sj[8];
        bool v[8];
        float e[8];
        #pragma unroll
        for (int j = 0; j < 8; j++) {
            int idx = i0 + j;
            v[j] = (idx < deg);
            sj[j] = __ldg(&slots[v[j] ? idx : 0]);
        }
        // dot phase: zs has a short live range (compiler picks MLP vs regs)
        #pragma unroll
        for (int j = 0; j < 8; j++) {
            float4 zs = zb4[(size_t)sj[j] * 16 + hl];
            float p = zs.x * zd.x;
            p = fmaf(zs.y, zd.y, p);
            p = fmaf(zs.z, zd.z, p);
            p = fmaf(zs.w, zd.w, p);
            p += __shfl_xor_sync(0xffffffffu, p, 8);
            p += __shfl_xor_sync(0xffffffffu, p, 4);
            p += __shfl_xor_sync(0xffffffffu, p, 2);
            p += __shfl_xor_sync(0xffffffffu, p, 1);
            float lr = (p > 0.0f) ? p : SLOPE * p;
            e[j] = v[j] ? lr : -3.0e38f;
        }
        float M = fmaxf(fmaxf(fmaxf(e[0], e[1]), fmaxf(e[2], e[3])),
                        fmaxf(fmaxf(e[4], e[5]), fmaxf(e[6], e[7])));
        float dc = 0.0f;
        float pe[8];
        #pragma unroll
        for (int j = 0; j < 8; j++) {
            pe[j] = v[j] ? __expf(e[j] - M) : 0.0f;
            dc += pe[j];
        }
        // accumulation phase: reload z rows (L1 hits; asm defeats CSE)
        float cx = 0.0f, cy = 0.0f, cz = 0.0f, cw = 0.0f;
        #pragma unroll
        for (int j = 0; j < 8; j++) {
            float4 zs = ld_nc_v4(&zb4[(size_t)sj[j] * 16 + hl]);
            cx = fmaf(pe[j], zs.x, cx);
            cy = fmaf(pe[j], zs.y, cy);
            cz = fmaf(pe[j], zs.z, cz);
            cw = fmaf(pe[j], zs.w, cw);
        }
        // branchless merge: one of the two exps is exp(0)=1
        float mn = fmaxf(m, M);
        float s0 = __expf(m - mn);
        float s1 = __expf(M - mn);
        d  = d  * s0 + dc * s1;
        ax = ax * s0 + cx * s1;
        ay = ay * s0 + cy * s1;
        az = az * s0 + cz * s1;
        aw = aw * s0 + cw * s1;
        m = mn;
    }

    float h0 = (d > 0.0f) ? ax / d : 0.0f;
    float h1 = (d > 0.0f) ? ay / d : 0.0f;
    float h2 = (d > 0.0f) ? az / d : 0.0f;
    float h3 = (d > 0.0f) ? aw / d : 0.0f;
    h0 = (h0 > 0.0f) ? h0 : expm1f(h0);
    h1 = (h1 > 0.0f) ? h1 : expm1f(h1);
    h2 = (h2 > 0.0f) ? h2 : expm1f(h2);
    h3 = (h3 > 0.0f) ? h3 : expm1f(h3);

    float4 hv; hv.x = h0; hv.y = h1; hv.z = h2; hv.w = h3;
    ((float4*)out)[(size_t)node * 16 + hl] = hv;
}

// ---------------- launch -----------------------------------------------------
extern "C" void kernel_launch(void* const* d_in, const int* in_sizes, int n_in,
                              void* d_out, int out_size) {
    const float* d_sim     = (const float*)d_in[0];
    const float* m_sim     = (const float*)d_in[1];
    const float* W_d       = (const float*)d_in[2];
    const float* W_m       = (const float*)d_in[3];
    const int*   node_type = (const int*)  d_in[4];
    const int*   src       = (const int*)  d_in[5];
    const int*   dst       = (const int*)  d_in[6];
    float* out = (float*)d_out;

    (void)in_sizes; (void)n_in; (void)out_size;

    int nblk_nodes = (N_NODES + 255) / 256;

    prep_kernel<<<nblk_nodes, 256>>>();
    build_kernel<<<nblk_nodes, 256>>>(node_type);

    work_kernel<<<PROJ_BLOCKS + SCAT_BLOCKS, 256>>>(d_sim, m_sim, W_d, W_m,
                                                    src, dst);

    // 2 nodes per warp -> 25000 warps -> 3125 blocks of 256 threads
    int agg_blocks = (N_NODES / 2 * 32 + 255) / 256;
    aggregate_kernel<<<agg_blocks, 256>>>(out);
}

// round 17
// speedup vs baseline: 1.0485x; 1.0485x over previous
#include <cuda_runtime.h>
#include <math.h>

#define N_NODES 50000
#define N_EDGES 1250000
#define D_SIMD  256
#define F_ATTN  64
#define SLOPE   0.2f
#define CAP     128      // max in-degree capacity (Poisson(25): max ~55 for this fixed input)

#define SCAT_BLOCKS 1184
#define PROJ_BLOCKS 392

// ---------------- scratch (device globals; no allocations allowed) ----------
__device__ float g_z[N_NODES * F_ATTN];              // projected features [N,64]
__device__ int   g_counts[N_NODES];                  // in-degree / slot cursor
__device__ int   g_slots[(size_t)N_NODES * CAP];     // src node per dst slot
__device__ int   g_list[2][N_NODES];                 // nodes partitioned by type
__device__ int   g_cnt2[2];                          // list sizes

// ---------------- packed f32x2 helpers ---------------------------------------
__device__ __forceinline__ unsigned long long pack2_dup(float x) {
    unsigned long long r;
    asm("mov.b64 %0, {%1, %1};" : "=l"(r) : "f"(x));
    return r;
}
__device__ __forceinline__ void ffma2(unsigned long long &c,
                                      unsigned long long a,
                                      unsigned long long b) {
    asm("fma.rn.f32x2 %0, %1, %2, %0;" : "+l"(c) : "l"(a), "l"(b));
}
// reload that the compiler cannot CSE with the earlier C++ load
__device__ __forceinline__ float4 ld_nc_v4(const float4* p) {
    float4 v;
    asm("ld.global.nc.v4.f32 {%0,%1,%2,%3}, [%4];"
        : "=f"(v.x), "=f"(v.y), "=f"(v.z), "=f"(v.w) : "l"(p));
    return v;
}

// ---------------- KA: zero counters ------------------------------------------
__global__ void prep_kernel() {
    int n = blockIdx.x * blockDim.x + threadIdx.x;
    if (n < N_NODES) g_counts[n] = 0;
    if (n < 2) g_cnt2[n] = 0;
}

// ---------------- KA2: partition nodes by type -------------------------------
__global__ void build_kernel(const int* __restrict__ node_type) {
    int n = blockIdx.x * blockDim.x + threadIdx.x;
    if (n >= N_NODES) return;
    int t = node_type[n];                  // 1 -> d_sim@W_d ; 0 -> m_sim@W_m
    int w = (t == 1) ? 1 : 0;
    int p = atomicAdd(&g_cnt2[w], 1);
    g_list[w][p] = n;
}

// ---------------- KB: fused scatter + projection (R9 configuration) ----------
__global__ void __launch_bounds__(256, 3) work_kernel(
    const float* __restrict__ d_sim,
    const float* __restrict__ m_sim,
    const float* __restrict__ W_d,
    const float* __restrict__ W_m,
    const int*   __restrict__ src,
    const int*   __restrict__ dst)
{
    __shared__ float sW[128 * F_ATTN];          // 32 KB k-chunk of W

    if (blockIdx.x < SCAT_BLOCKS) {
        const int stride = SCAT_BLOCKS * 256;
        for (int j = blockIdx.x * 256 + threadIdx.x; j < N_EDGES; j += stride) {
            int d = dst[j];
            int pos = atomicAdd(&g_counts[d], 1);
            if (pos < CAP) g_slots[(size_t)d * CAP + pos] = src[j];
        }
        return;
    }

    const int pgrid = gridDim.x - SCAT_BLOCKS;
    const int pbid  = blockIdx.x - SCAT_BLOCKS;

    const int cnt1 = g_cnt2[1];
    const int cnt0 = g_cnt2[0];
    const int tiles1 = (cnt1 + 127) >> 7;
    const int tiles0 = (cnt0 + 127) >> 7;
    const int total = tiles1 + tiles0;

    const int fgrp = threadIdx.x & 7;
    const int ngrp = threadIdx.x >> 3;          // 0..31
    const int fb = fgrp * 8;

    for (int t = pbid; t < total; t += pgrid) {
        const int w   = (t < tiles1) ? 1 : 0;
        const int lt  = (w == 1) ? t : (t - tiles1);
        const float* __restrict__ sim = (w == 1) ? d_sim : m_sim;
        const float* __restrict__ W   = (w == 1) ? W_d  : W_m;
        const int*   __restrict__ list = g_list[w];
        const int count = (w == 1) ? cnt1 : cnt0;

        const int base = lt * 128;
        int n[4]; bool valid[4];
        const float4* sv[4];
        unsigned long long acc2[4][4];
        #pragma unroll
        for (int i = 0; i < 4; i++) {
            int li = base + ngrp + 32 * i;
            valid[i] = (li < count);
            n[i] = valid[i] ? list[li] : 0;
            sv[i] = (const float4*)(sim + (size_t)n[i] * D_SIMD);
            #pragma unroll
            for (int j = 0; j < 4; j++) acc2[i][j] = 0ull;
        }

        for (int kt = 0; kt < 2; kt++) {
            __syncthreads();
            {
                const float4* w4 = (const float4*)(W + kt * 128 * F_ATTN);
                float4* s4 = (float4*)sW;
                for (int idx = threadIdx.x; idx < 128 * F_ATTN / 4; idx += 256)
                    s4[idx] = w4[idx];
            }
            __syncthreads();

            #pragma unroll 4
            for (int k4 = 0; k4 < 32; k4++) {
                float4 s4v[4];
                #pragma unroll
                for (int i = 0; i < 4; i++) s4v[i] = sv[i][kt * 32 + k4];
                #pragma unroll
                for (int c = 0; c < 4; c++) {
                    int kl = k4 * 4 + c;
                    const ulonglong2* wp =
                        (const ulonglong2*)&sW[kl * F_ATTN + fb];
                    ulonglong2 wA = wp[0];
                    ulonglong2 wB = wp[1];
                    #pragma unroll
                    for (int i = 0; i < 4; i++) {
                        float sk = (c == 0) ? s4v[i].x :
                                   (c == 1) ? s4v[i].y :
                                   (c == 2) ? s4v[i].z : s4v[i].w;
                        unsigned long long sk2 = pack2_dup(sk);
                        ffma2(acc2[i][0], wA.x, sk2);
                        ffma2(acc2[i][1], wA.y, sk2);
                        ffma2(acc2[i][2], wB.x, sk2);
                        ffma2(acc2[i][3], wB.y, sk2);
                    }
                }
            }
        }

        #pragma unroll
        for (int i = 0; i < 4; i++) {
            if (valid[i]) {
                ulonglong2* zp = (ulonglong2*)&g_z[(size_t)n[i] * F_ATTN + fb];
                ulonglong2 v0; v0.x = acc2[i][0]; v0.y = acc2[i][1];
                ulonglong2 v1; v1.x = acc2[i][2]; v1.y = acc2[i][3];
                zp[0] = v0;
                zp[1] = v1;
            }
        }
    }
}

// ---------------- KC: chunked-softmax aggregation + ELU ----------------------
// FOUR nodes per warp: lane group g = lane>>3 owns node wg*4+g; each lane
// holds 8 feature cols (2x float4). Dot reduce = 3 shfl within 8-lane group.
// Slot indices fetched as int4 pairs. Padded edges carry e=-3e38 -> pe=0.
__global__ void __launch_bounds__(256) aggregate_kernel(float* __restrict__ out) {
    int wg   = (blockIdx.x * blockDim.x + threadIdx.x) >> 5;
    int lane = threadIdx.x & 31;
    int g    = lane >> 3;          // node slot in warp
    int gl   = lane & 7;           // lane within 8-lane group
    int node = wg * 4 + g;
    if (node >= N_NODES) return;

    int deg = g_counts[node];
    if (deg > CAP) deg = CAP;
    int dmax = deg;
    dmax = max(dmax, __shfl_xor_sync(0xffffffffu, dmax, 8));
    dmax = max(dmax, __shfl_xor_sync(0xffffffffu, dmax, 16));
    int nch = (dmax + 7) >> 3;

    const float4* zb4 = (const float4*)g_z;
    float4 zd0 = zb4[(size_t)node * 16 + gl * 2];
    float4 zd1 = zb4[(size_t)node * 16 + gl * 2 + 1];
    const int* slots = g_slots + (size_t)node * CAP;

    float m = -3.0e38f, d = 0.0f;
    float4 A0 = make_float4(0.f, 0.f, 0.f, 0.f);
    float4 A1 = make_float4(0.f, 0.f, 0.f, 0.f);

    for (int c = 0; c < nch; c++) {
        int i0 = c * 8;
        // slot indices (stale/garbage beyond deg are still valid node ids or 0;
        // their contributions are forced to zero via the pe select)
        int4 sa = *(const int4*)&slots[i0];
        int4 sb = *(const int4*)&slots[i0 + 4];
        int sj[8] = {sa.x, sa.y, sa.z, sa.w, sb.x, sb.y, sb.z, sb.w};

        float e[8];
        #pragma unroll
        for (int j = 0; j < 8; j++) {
            const float4* zp = &zb4[(size_t)sj[j] * 16 + gl * 2];
            float4 a = zp[0];
            float4 b = zp[1];
            float p = a.x * zd0.x;
            p = fmaf(a.y, zd0.y, p);
            p = fmaf(a.z, zd0.z, p);
            p = fmaf(a.w, zd0.w, p);
            p = fmaf(b.x, zd1.x, p);
            p = fmaf(b.y, zd1.y, p);
            p = fmaf(b.z, zd1.z, p);
            p = fmaf(b.w, zd1.w, p);
            p += __shfl_xor_sync(0xffffffffu, p, 4);
            p += __shfl_xor_sync(0xffffffffu, p, 2);
            p += __shfl_xor_sync(0xffffffffu, p, 1);
            float lr = fmaxf(p, SLOPE * p);         // leaky_relu, branchless
            e[j] = (i0 + j < deg) ? lr : -3.0e38f;
        }
        float M = fmaxf(fmaxf(fmaxf(e[0], e[1]), fmaxf(e[2], e[3])),
                        fmaxf(fmaxf(e[4], e[5]), fmaxf(e[6], e[7])));
        float pe[8];
        float dc = 0.0f;
        #pragma unroll
        for (int j = 0; j < 8; j++) {
            pe[j] = (i0 + j < deg) ? __expf(e[j] - M) : 0.0f;
            dc += pe[j];
        }
        float4 C0 = make_float4(0.f, 0.f, 0.f, 0.f);
        float4 C1 = make_float4(0.f, 0.f, 0.f, 0.f);
        #pragma unroll
        for (int j = 0; j < 8; j++) {
            const float4* zp = &zb4[(size_t)sj[j] * 16 + gl * 2];
            float4 a = ld_nc_v4(zp);                // L1-hit reload
            float4 b = ld_nc_v4(zp + 1);
            C0.x = fmaf(pe[j], a.x, C0.x);
            C0.y = fmaf(pe[j], a.y, C0.y);
            C0.z = fmaf(pe[j], a.z, C0.z);
            C0.w = fmaf(pe[j], a.w, C0.w);
            C1.x = fmaf(pe[j], b.x, C1.x);
            C1.y = fmaf(pe[j], b.y, C1.y);
            C1.z = fmaf(pe[j], b.z, C1.z);
            C1.w = fmaf(pe[j], b.w, C1.w);
        }
        // branchless merge: one of the two exps is exp(0)=1
        float mn = fmaxf(m, M);
        float s0 = __expf(m - mn);
        float s1 = __expf(M - mn);
        d = d * s0 + dc * s1;
        A0.x = A0.x * s0 + C0.x * s1;
        A0.y = A0.y * s0 + C0.y * s1;
        A0.z = A0.z * s0 + C0.z * s1;
        A0.w = A0.w * s0 + C0.w * s1;
        A1.x = A1.x * s0 + C1.x * s1;
        A1.y = A1.y * s0 + C1.y * s1;
        A1.z = A1.z * s0 + C1.z * s1;
        A1.w = A1.w * s0 + C1.w * s1;
        m = mn;
    }

    float inv = (d > 0.0f) ? 1.0f / d : 0.0f;
    float h[8];
    h[0] = A0.x * inv; h[1] = A0.y * inv; h[2] = A0.z * inv; h[3] = A0.w * inv;
    h[4] = A1.x * inv; h[5] = A1.y * inv; h[6] = A1.z * inv; h[7] = A1.w * inv;
    #pragma unroll
    for (int j = 0; j < 8; j++)
        h[j] = (h[j] > 0.0f) ? h[j] : expm1f(h[j]);

    float4* op = (float4*)out + (size_t)node * 16 + gl * 2;
    op[0] = make_float4(h[0], h[1], h[2], h[3]);
    op[1] = make_float4(h[4], h[5], h[6], h[7]);
}

// ---------------- launch -----------------------------------------------------
extern "C" void kernel_launch(void* const* d_in, const int* in_sizes, int n_in,
                              void* d_out, int out_size) {
    const float* d_sim     = (const float*)d_in[0];
    const float* m_sim     = (const float*)d_in[1];
    const float* W_d       = (const float*)d_in[2];
    const float* W_m       = (const float*)d_in[3];
    const int*   node_type = (const int*)  d_in[4];
    const int*   src       = (const int*)  d_in[5];
    const int*   dst       = (const int*)  d_in[6];
    float* out = (float*)d_out;

    (void)in_sizes; (void)n_in; (void)out_size;

    int nblk_nodes = (N_NODES + 255) / 256;

    prep_kernel<<<nblk_nodes, 256>>>();
    build_kernel<<<nblk_nodes, 256>>>(node_type);

    work_kernel<<<SCAT_BLOCKS + PROJ_BLOCKS, 256>>>(d_sim, m_sim, W_d, W_m,
                                                    src, dst);

    // 4 nodes per warp -> 12500 warps -> 1563 blocks of 256 threads
    int agg_blocks = ((N_NODES + 3) / 4 * 32 + 255) / 256;
    aggregate_kernel<<<agg_blocks, 256>>>(out);
}